// round 2
// baseline (speedup 1.0000x reference)
#include <cuda_runtime.h>
#include <math.h>

#define F_BINS   16384
#define W_HALF   1024
#define TAPS     (2*W_HALF)            // 2048
#define NBUF_LEN (F_BINS + 2*W_HALF)   // 18432
#define NCH      48
#define NCT      96
#define HW_IN    (512*512)

// scratch (static device globals -- no allocation)
__device__ __align__(16) unsigned int g_hist[192 * F_BINS];   // 12.6 MB
__device__ __align__(16) float g_T[NCT * 257];

// separable resize taps: interior [1,3,3,1]/8, edges renormalized /7
__device__ __forceinline__ void taps_w(int o, int* idx, float* w) {
    int b = 2*o - 1;
    float w0 = (o == 0)   ? 0.f : 1.f;
    float w3 = (o == 255) ? 0.f : 1.f;
    float inv = (o == 0 || o == 255) ? (1.f/7.f) : (1.f/8.f);
    idx[0] = b < 0 ? 0 : b;
    idx[1] = b + 1;
    idx[2] = b + 2;
    idx[3] = (b + 3 > 511) ? 511 : (b + 3);
    w[0] = w0*inv; w[1] = 3.f*inv; w[2] = 3.f*inv; w[3] = w3*inv;
}

// ---- k1: fused antialiased 2x downsample + fine count histogram ----
__global__ void __launch_bounds__(512) k1_hist(const float* __restrict__ pred,
                                               const float* __restrict__ tgt) {
    extern __shared__ unsigned int sh_hist[];   // 16384 uints = 64 KB
    const int ct   = blockIdx.x;   // 0..95
    const int half = blockIdx.y;   // 0..1 (output row halves)
    const int tid  = threadIdx.x;

    const float* src = (ct < NCH) ? (pred + (size_t)ct * HW_IN)
                                  : (tgt  + (size_t)(ct - NCH) * HW_IN);

    for (int i = tid; i < F_BINS; i += 512) sh_hist[i] = 0u;
    __syncthreads();

    for (int p = tid; p < 128*256; p += 512) {
        int oy = (half << 7) + (p >> 8);
        int ox = p & 255;
        int iy[4]; float wy[4]; taps_w(oy, iy, wy);
        int ix[4]; float wx[4]; taps_w(ox, ix, wx);
        float v = 0.f;
        #pragma unroll
        for (int r = 0; r < 4; r++) {
            const float* row = src + (size_t)iy[r] * 512;
            float h = wx[0]*row[ix[0]] + wx[1]*row[ix[1]]
                    + wx[2]*row[ix[2]] + wx[3]*row[ix[3]];
            v += wy[r] * h;
        }
        int bin = (int)(v * 16384.f);
        bin = bin < 0 ? 0 : (bin > 16383 ? 16383 : bin);
        atomicAdd(&sh_hist[bin], 1u);
    }
    __syncthreads();

    unsigned int* dst = g_hist + (size_t)(ct*2 + half) * F_BINS;
    const uint4* s4 = reinterpret_cast<const uint4*>(sh_hist);
    uint4* d4 = reinterpret_cast<uint4*>(dst);
    for (int i = tid; i < F_BINS/4; i += 512) d4[i] = s4[i];
}

// ---- k2: T(m) = suffix_count + windowed sigmoid-table dot ----
__global__ void __launch_bounds__(512) k2_T(void) {
    extern __shared__ float sm[];
    float* nbuf = sm;                   // [18432] padded fine hist (f32)
    float* tab  = sm + NBUF_LEN;        // [2048] sigmoid table
    float* csuf = tab + TAPS;           // [256] chunk suffix sums
    __shared__ float chunk[256];

    const int ct = blockIdx.x, tid = threadIdx.x;
    const unsigned int* a = g_hist + (size_t)(2*ct)   * F_BINS;
    const unsigned int* b = g_hist + (size_t)(2*ct+1) * F_BINS;

    for (int i = tid; i < W_HALF; i += 512) {
        nbuf[i] = 0.f;
        nbuf[W_HALF + F_BINS + i] = 0.f;
    }
    for (int k = tid; k < F_BINS; k += 512)
        nbuf[W_HALF + k] = (float)(a[k] + b[k]);
    for (int j = tid; j < TAPS; j += 512) {
        float u = 0.018310546875f * ((float)j - 1023.5f);  // 300/16384 * (j - W + 0.5)
        tab[j] = 1.f / (1.f + expf(-u));
    }
    __syncthreads();

    // 64-bin chunk sums
    if (tid < 256) {
        const float4* p4 = reinterpret_cast<const float4*>(nbuf + W_HALF) + tid*16;
        float s = 0.f;
        #pragma unroll
        for (int q = 0; q < 16; q++) { float4 v = p4[q]; s += v.x+v.y+v.z+v.w; }
        chunk[tid] = s;
    }
    __syncthreads();
    // suffix scan of 256 chunks (warp 0)
    if (tid < 32) {
        float loc[8];
        float run = 0.f;
        #pragma unroll
        for (int i = 7; i >= 0; i--) { run += chunk[tid*8 + i]; loc[i] = run; }
        float t_l = run, suf = run;
        #pragma unroll
        for (int off = 1; off < 32; off <<= 1) {
            float v = __shfl_down_sync(0xffffffffu, suf, off);
            if (tid + off < 32) suf += v;
        }
        float above = suf - t_l;
        #pragma unroll
        for (int i = 0; i < 8; i++) csuf[tid*8 + i] = loc[i] + above;
    }
    __syncthreads();

    const int warp = tid >> 5, lane = tid & 31;
    const float4* nb4 = reinterpret_cast<const float4*>(nbuf);
    const float4* tb4 = reinterpret_cast<const float4*>(tab);
    for (int m = warp; m <= 256; m += 16) {
        const float4* base = nb4 + m*16;   // nbuf float offset 64*m
        float acc = 0.f;
        #pragma unroll
        for (int q = 0; q < 16; q++) {
            float4 x = base[q*32 + lane];
            float4 t = tb4[q*32 + lane];
            acc += x.x*t.x + x.y*t.y + x.z*t.z + x.w*t.w;
        }
        #pragma unroll
        for (int off = 16; off; off >>= 1)
            acc += __shfl_down_sync(0xffffffffu, acc, off);
        if (lane == 0) {
            int c = m + 16;
            float S = (c < 256) ? csuf[c] : 0.f;
            g_T[ct*257 + m] = S + acc;
        }
    }
}

// ---- k3: CDF L1 reduction to scalar ----
__global__ void __launch_bounds__(512) k3_loss(float* __restrict__ out) {
    __shared__ float red[16];
    const int tid = threadIdx.x;
    float s = 0.f;
    for (int e = tid; e < NCH*256; e += 512) {
        int p  = e >> 8;
        int bb = e & 255;
        const float* Tp = g_T + p*257;
        const float* Tt = g_T + (NCH + p)*257;
        float p0 = Tp[0], t0 = Tt[0];
        float invp = 1.f / (p0 - Tp[256]);
        float invt = 1.f / (t0 - Tt[256]);
        float cp  = (p0 - Tp[bb+1]) * invp;
        float ctv = (t0 - Tt[bb+1]) * invt;
        s += fabsf(cp - ctv);
    }
    #pragma unroll
    for (int off = 16; off; off >>= 1) s += __shfl_down_sync(0xffffffffu, s, off);
    if ((tid & 31) == 0) red[tid >> 5] = s;
    __syncthreads();
    if (tid < 32) {
        float v = (tid < 16) ? red[tid] : 0.f;
        #pragma unroll
        for (int off = 16; off; off >>= 1) v += __shfl_down_sync(0xffffffffu, v, off);
        if (tid == 0) out[0] = v * (1.0f / (48.0f * 256.0f));
    }
}

extern "C" void kernel_launch(void* const* d_in, const int* in_sizes, int n_in,
                              void* d_out, int out_size) {
    const float* pred = (const float*)d_in[0];
    const float* tgt  = (const float*)d_in[1];
    float* out = (float*)d_out;

    cudaFuncSetAttribute(k1_hist, cudaFuncAttributeMaxDynamicSharedMemorySize, 65536);
    cudaFuncSetAttribute(k2_T,    cudaFuncAttributeMaxDynamicSharedMemorySize, NBUF_LEN*4 + TAPS*4 + 256*4);

    k1_hist<<<dim3(NCT, 2), 512, 65536>>>(pred, tgt);
    k2_T<<<NCT, 512, NBUF_LEN*4 + TAPS*4 + 256*4>>>();
    k3_loss<<<1, 512>>>(out);
}

// round 3
// speedup vs baseline: 1.2360x; 1.2360x over previous
#include <cuda_runtime.h>
#include <math.h>

#define F_BINS   16384
#define W_HALF   1024
#define TAPS     (2*W_HALF)            // 2048
#define NBUF_LEN (F_BINS + 2*W_HALF)   // 18432
#define NCH      48
#define NCT      96
#define NSLICE   3
#define HW_IN    (512*512)
#define BROWS    16                    // output rows per staging block
#define HROWS    (2*BROWS + 2)         // 34 h-filtered rows staged

// scratch (static device globals -- no allocation)
__device__ __align__(16) unsigned int g_hist[NCT * NSLICE * F_BINS];  // 18.9 MB
__device__ __align__(16) float g_T[NCT * 257];

#define K1_SMEM (F_BINS*4 + HROWS*256*4)                 // 65536 + 34816 = 100352
#define K2_SMEM (NBUF_LEN*4 + 256*4)                     // 74752

// ---- k1: separable antialiased 2x downsample (shfl h-pass) + fine histogram ----
__global__ void __launch_bounds__(512) k1_hist(const float* __restrict__ pred,
                                               const float* __restrict__ tgt) {
    extern __shared__ unsigned char smraw[];
    unsigned int* sh_hist = reinterpret_cast<unsigned int*>(smraw);
    float* sh_h = reinterpret_cast<float*>(smraw + F_BINS*4);   // [HROWS][256]

    const int ct    = blockIdx.x;   // 0..95
    const int slice = blockIdx.y;   // 0..2
    const int tid   = threadIdx.x;
    const int warp  = tid >> 5, lane = tid & 31;
    const unsigned FULL = 0xffffffffu;

    const int r0 = (slice == 0) ? 0   : (slice == 1 ? 85  : 170);
    const int r1 = (slice == 0) ? 85  : (slice == 1 ? 170 : 256);

    const float* src = (ct < NCH) ? (pred + (size_t)ct * HW_IN)
                                  : (tgt  + (size_t)(ct - NCH) * HW_IN);

    for (int i = tid; i < F_BINS; i += 512) sh_hist[i] = 0u;
    __syncthreads();

    for (int oyb = r0; oyb < r1; oyb += BROWS) {
        // ---- stage HROWS horizontally-filtered input rows ----
        for (int lr = warp; lr < HROWS; lr += 16) {
            int iy = 2*oyb - 1 + lr;
            iy = iy < 0 ? 0 : (iy > 511 ? 511 : iy);
            const float4* row4 = reinterpret_cast<const float4*>(src + (size_t)iy * 512);
            float4 v0 = row4[lane];
            float4 v1 = row4[32 + lane];
            float4 v2 = row4[64 + lane];
            float4 v3 = row4[96 + lane];
            // cross-chunk carries (broadcasts, warp-uniform)
            float cl1 = __shfl_sync(FULL, v0.w, 31);
            float cl2 = __shfl_sync(FULL, v1.w, 31);
            float cl3 = __shfl_sync(FULL, v2.w, 31);
            float cr0 = __shfl_sync(FULL, v1.x, 0);
            float cr1 = __shfl_sync(FULL, v2.x, 0);
            float cr2 = __shfl_sync(FULL, v3.x, 0);
            float carryL[4] = {0.f, cl1, cl2, cl3};
            float carryR[4] = {cr0, cr1, cr2, 0.f};
            float4 vv[4] = {v0, v1, v2, v3};
            float2* hd = reinterpret_cast<float2*>(sh_h + lr*256);
            #pragma unroll
            for (int c = 0; c < 4; c++) {
                float4 v = vv[c];
                float left  = __shfl_up_sync(FULL, v.w, 1);
                if (lane == 0)  left  = carryL[c];
                float right = __shfl_down_sync(FULL, v.x, 1);
                if (lane == 31) right = carryR[c];
                float ha, hb;
                if (c == 0 && lane == 0)
                    ha = (3.f*v.x + 3.f*v.y + v.z) * (1.f/7.f);
                else
                    ha = (left + 3.f*v.x + 3.f*v.y + v.z) * 0.125f;
                if (c == 3 && lane == 31)
                    hb = (v.y + 3.f*v.z + 3.f*v.w) * (1.f/7.f);
                else
                    hb = (v.y + 3.f*v.z + 3.f*v.w + right) * 0.125f;
                hd[c*32 + lane] = make_float2(ha, hb);
            }
        }
        __syncthreads();

        // ---- vertical combine + histogram insert ----
        int nrows = r1 - oyb; if (nrows > BROWS) nrows = BROWS;
        int npix = nrows * 256;
        for (int p = tid; p < npix; p += 512) {
            int oyl = p >> 8;
            int ox  = p & 255;
            int oy  = oyb + oyl;
            const float* hp = sh_h + (2*oyl)*256 + ox;
            float a0 = hp[0], a1 = hp[256], a2 = hp[512], a3 = hp[768];
            float inv = (oy == 0 || oy == 255) ? (1.f/7.f) : 0.125f;
            float w0 = (oy == 0)   ? 0.f : inv;
            float w3 = (oy == 255) ? 0.f : inv;
            float val = w0*a0 + 3.f*inv*(a1 + a2) + w3*a3;
            int bin = (int)(val * 16384.f);
            bin = bin < 0 ? 0 : (bin > 16383 ? 16383 : bin);
            atomicAdd(&sh_hist[bin], 1u);
        }
        __syncthreads();
    }

    unsigned int* dst = g_hist + (size_t)(ct*NSLICE + slice) * F_BINS;
    const uint4* s4 = reinterpret_cast<const uint4*>(sh_hist);
    uint4* d4 = reinterpret_cast<uint4*>(dst);
    for (int i = tid; i < F_BINS/4; i += 512) d4[i] = s4[i];
}

// ---- k2: T(m) = suffix_count + windowed sigmoid dot (table in registers) ----
__global__ void __launch_bounds__(512) k2_T(void) {
    extern __shared__ float sm[];
    float* nbuf = sm;                   // [18432] padded fine hist (f32)
    float* csuf = sm + NBUF_LEN;        // [256] chunk suffix sums
    __shared__ float chunk[256];

    const int ct = blockIdx.x, tid = threadIdx.x;
    const int warp = tid >> 5, lane = tid & 31;
    const unsigned int* a = g_hist + (size_t)(3*ct)     * F_BINS;
    const unsigned int* b = g_hist + (size_t)(3*ct + 1) * F_BINS;
    const unsigned int* c = g_hist + (size_t)(3*ct + 2) * F_BINS;

    for (int i = tid; i < W_HALF; i += 512) {
        nbuf[i] = 0.f;
        nbuf[W_HALF + F_BINS + i] = 0.f;
    }
    for (int k = tid; k < F_BINS; k += 512)
        nbuf[W_HALF + k] = (float)(a[k] + b[k] + c[k]);

    // per-thread sigmoid table: 16 float4 = taps j = 4*(q*32+lane)+s
    float4 t[16];
    #pragma unroll
    for (int q = 0; q < 16; q++) {
        float j0 = (float)(128*q + 4*lane);
        t[q].x = 1.f / (1.f + expf(-0.018310546875f * (j0 + 0.f - 1023.5f)));
        t[q].y = 1.f / (1.f + expf(-0.018310546875f * (j0 + 1.f - 1023.5f)));
        t[q].z = 1.f / (1.f + expf(-0.018310546875f * (j0 + 2.f - 1023.5f)));
        t[q].w = 1.f / (1.f + expf(-0.018310546875f * (j0 + 3.f - 1023.5f)));
    }
    __syncthreads();

    // 64-bin chunk sums
    if (tid < 256) {
        const float4* p4 = reinterpret_cast<const float4*>(nbuf + W_HALF) + tid*16;
        float s = 0.f;
        #pragma unroll
        for (int q = 0; q < 16; q++) { float4 v = p4[q]; s += v.x+v.y+v.z+v.w; }
        chunk[tid] = s;
    }
    __syncthreads();
    if (tid < 32) {      // suffix scan of 256 chunks
        float loc[8];
        float run = 0.f;
        #pragma unroll
        for (int i = 7; i >= 0; i--) { run += chunk[tid*8 + i]; loc[i] = run; }
        float t_l = run, suf = run;
        #pragma unroll
        for (int off = 1; off < 32; off <<= 1) {
            float v = __shfl_down_sync(0xffffffffu, suf, off);
            if (tid + off < 32) suf += v;
        }
        float above = suf - t_l;
        #pragma unroll
        for (int i = 0; i < 8; i++) csuf[tid*8 + i] = loc[i] + above;
    }
    __syncthreads();

    const float4* nb4 = reinterpret_cast<const float4*>(nbuf);
    for (int m = warp; m <= 256; m += 16) {
        const float4* base = nb4 + m*16;
        float acc = 0.f;
        #pragma unroll
        for (int q = 0; q < 16; q++) {
            float4 x = base[q*32 + lane];
            acc += x.x*t[q].x + x.y*t[q].y + x.z*t[q].z + x.w*t[q].w;
        }
        #pragma unroll
        for (int off = 16; off; off >>= 1)
            acc += __shfl_down_sync(0xffffffffu, acc, off);
        if (lane == 0) {
            int cc = m + 16;
            float S = (cc < 256) ? csuf[cc] : 0.f;
            g_T[ct*257 + m] = S + acc;
        }
    }
}

// ---- k3: CDF L1 reduction to scalar ----
__global__ void __launch_bounds__(512) k3_loss(float* __restrict__ out) {
    __shared__ float red[16];
    const int tid = threadIdx.x;
    float s = 0.f;
    for (int e = tid; e < NCH*256; e += 512) {
        int p  = e >> 8;
        int bb = e & 255;
        const float* Tp = g_T + p*257;
        const float* Tt = g_T + (NCH + p)*257;
        float p0 = Tp[0], t0 = Tt[0];
        float invp = 1.f / (p0 - Tp[256]);
        float invt = 1.f / (t0 - Tt[256]);
        float cp  = (p0 - Tp[bb+1]) * invp;
        float ctv = (t0 - Tt[bb+1]) * invt;
        s += fabsf(cp - ctv);
    }
    #pragma unroll
    for (int off = 16; off; off >>= 1) s += __shfl_down_sync(0xffffffffu, s, off);
    if ((tid & 31) == 0) red[tid >> 5] = s;
    __syncthreads();
    if (tid < 32) {
        float v = (tid < 16) ? red[tid] : 0.f;
        #pragma unroll
        for (int off = 16; off; off >>= 1) v += __shfl_down_sync(0xffffffffu, v, off);
        if (tid == 0) out[0] = v * (1.0f / (48.0f * 256.0f));
    }
}

extern "C" void kernel_launch(void* const* d_in, const int* in_sizes, int n_in,
                              void* d_out, int out_size) {
    const float* pred = (const float*)d_in[0];
    const float* tgt  = (const float*)d_in[1];
    float* out = (float*)d_out;

    cudaFuncSetAttribute(k1_hist, cudaFuncAttributeMaxDynamicSharedMemorySize, K1_SMEM);
    cudaFuncSetAttribute(k2_T,    cudaFuncAttributeMaxDynamicSharedMemorySize, K2_SMEM);

    k1_hist<<<dim3(NCT, NSLICE), 512, K1_SMEM>>>(pred, tgt);
    k2_T<<<NCT, 512, K2_SMEM>>>();
    k3_loss<<<1, 512>>>(out);
}

// round 4
// speedup vs baseline: 1.6878x; 1.3655x over previous
#include <cuda_runtime.h>
#include <math.h>

#define F_BINS   4096
#define W_HALF   256
#define TAPS     (2*W_HALF)            // 512
#define NBUF_LEN (F_BINS + 2*W_HALF)   // 4608
#define NCH      48
#define NCT      96
#define NSLICE   4
#define HW_IN    (512*512)
#define BROWS    16
#define HROWS    (2*BROWS + 2)         // 34
#define USTEP    0.0732421875f         // 300/4096

// scratch (static device globals -- no allocation)
__device__ __align__(16) unsigned int g_hist[NCT * NSLICE * F_BINS];  // 6.3 MB
__device__ __align__(16) float g_T[NCT * 257];

#define K1_SMEM (F_BINS*4 + HROWS*256*4)   // 16384 + 34816 = 51200

// ---- k1: separable antialiased 2x downsample (shfl h-pass) + fine histogram ----
__global__ void __launch_bounds__(512) k1_hist(const float* __restrict__ pred,
                                               const float* __restrict__ tgt) {
    extern __shared__ unsigned char smraw[];
    unsigned int* sh_hist = reinterpret_cast<unsigned int*>(smraw);
    float* sh_h = reinterpret_cast<float*>(smraw + F_BINS*4);   // [HROWS][256]

    const int ct    = blockIdx.x;   // 0..95
    const int slice = blockIdx.y;   // 0..3
    const int tid   = threadIdx.x;
    const int warp  = tid >> 5, lane = tid & 31;
    const unsigned FULL = 0xffffffffu;

    const int r0 = slice * 64;
    const int r1 = r0 + 64;

    const float* src = (ct < NCH) ? (pred + (size_t)ct * HW_IN)
                                  : (tgt  + (size_t)(ct - NCH) * HW_IN);

    for (int i = tid; i < F_BINS; i += 512) sh_hist[i] = 0u;
    __syncthreads();

    for (int oyb = r0; oyb < r1; oyb += BROWS) {
        // ---- stage HROWS horizontally-filtered input rows ----
        for (int lr = warp; lr < HROWS; lr += 16) {
            int iy = 2*oyb - 1 + lr;
            iy = iy < 0 ? 0 : (iy > 511 ? 511 : iy);
            const float4* row4 = reinterpret_cast<const float4*>(src + (size_t)iy * 512);
            float4 v0 = row4[lane];
            float4 v1 = row4[32 + lane];
            float4 v2 = row4[64 + lane];
            float4 v3 = row4[96 + lane];
            float cl1 = __shfl_sync(FULL, v0.w, 31);
            float cl2 = __shfl_sync(FULL, v1.w, 31);
            float cl3 = __shfl_sync(FULL, v2.w, 31);
            float cr0 = __shfl_sync(FULL, v1.x, 0);
            float cr1 = __shfl_sync(FULL, v2.x, 0);
            float cr2 = __shfl_sync(FULL, v3.x, 0);
            float carryL[4] = {0.f, cl1, cl2, cl3};
            float carryR[4] = {cr0, cr1, cr2, 0.f};
            float4 vv[4] = {v0, v1, v2, v3};
            float2* hd = reinterpret_cast<float2*>(sh_h + lr*256);
            #pragma unroll
            for (int c = 0; c < 4; c++) {
                float4 v = vv[c];
                float left  = __shfl_up_sync(FULL, v.w, 1);
                if (lane == 0)  left  = carryL[c];
                float right = __shfl_down_sync(FULL, v.x, 1);
                if (lane == 31) right = carryR[c];
                float ha, hb;
                if (c == 0 && lane == 0)
                    ha = (3.f*v.x + 3.f*v.y + v.z) * (1.f/7.f);
                else
                    ha = (left + 3.f*v.x + 3.f*v.y + v.z) * 0.125f;
                if (c == 3 && lane == 31)
                    hb = (v.y + 3.f*v.z + 3.f*v.w) * (1.f/7.f);
                else
                    hb = (v.y + 3.f*v.z + 3.f*v.w + right) * 0.125f;
                hd[c*32 + lane] = make_float2(ha, hb);
            }
        }
        __syncthreads();

        // ---- vertical combine + histogram insert ----
        for (int p = tid; p < BROWS*256; p += 512) {
            int oyl = p >> 8;
            int ox  = p & 255;
            int oy  = oyb + oyl;
            const float* hp = sh_h + (2*oyl)*256 + ox;
            float a0 = hp[0], a1 = hp[256], a2 = hp[512], a3 = hp[768];
            float inv = (oy == 0 || oy == 255) ? (1.f/7.f) : 0.125f;
            float w0 = (oy == 0)   ? 0.f : inv;
            float w3 = (oy == 255) ? 0.f : inv;
            float val = w0*a0 + 3.f*inv*(a1 + a2) + w3*a3;
            int bin = (int)(val * (float)F_BINS);
            bin = bin < 0 ? 0 : (bin > F_BINS-1 ? F_BINS-1 : bin);
            atomicAdd(&sh_hist[bin], 1u);
        }
        __syncthreads();
    }

    unsigned int* dst = g_hist + (size_t)(ct*NSLICE + slice) * F_BINS;
    const uint4* s4 = reinterpret_cast<const uint4*>(sh_hist);
    uint4* d4 = reinterpret_cast<uint4*>(dst);
    for (int i = tid; i < F_BINS/4; i += 512) d4[i] = s4[i];
}

// ---- k2: T(m) = suffix_count + windowed sigmoid dot (table in registers) ----
__global__ void __launch_bounds__(512) k2_T(void) {
    __shared__ float nbuf[NBUF_LEN];    // padded fine hist
    __shared__ float csuf[257];         // coarse-chunk suffix sums
    __shared__ float chunk[256];

    const int ct = blockIdx.x, tid = threadIdx.x;
    const int warp = tid >> 5, lane = tid & 31;
    const unsigned int* h0 = g_hist + (size_t)(NSLICE*ct) * F_BINS;

    if (tid < W_HALF) {
        nbuf[tid] = 0.f;
        nbuf[W_HALF + F_BINS + tid] = 0.f;
    }
    for (int k = tid; k < F_BINS; k += 512)
        nbuf[W_HALF + k] = (float)(h0[k] + h0[F_BINS + k]
                                 + h0[2*F_BINS + k] + h0[3*F_BINS + k]);

    // per-thread sigmoid table: 4 float4, taps j = 128q + 4lane + s
    float4 t[4];
    #pragma unroll
    for (int q = 0; q < 4; q++) {
        float j0 = (float)(128*q + 4*lane);
        t[q].x = 1.f / (1.f + expf(-USTEP * (j0 + 0.f - 255.5f)));
        t[q].y = 1.f / (1.f + expf(-USTEP * (j0 + 1.f - 255.5f)));
        t[q].z = 1.f / (1.f + expf(-USTEP * (j0 + 2.f - 255.5f)));
        t[q].w = 1.f / (1.f + expf(-USTEP * (j0 + 3.f - 255.5f)));
    }
    __syncthreads();

    // 16-bin chunk sums (one per coarse bin)
    if (tid < 256) {
        const float4* p4 = reinterpret_cast<const float4*>(nbuf + W_HALF) + tid*4;
        float4 v0 = p4[0], v1 = p4[1], v2 = p4[2], v3 = p4[3];
        chunk[tid] = (v0.x+v0.y+v0.z+v0.w) + (v1.x+v1.y+v1.z+v1.w)
                   + (v2.x+v2.y+v2.z+v2.w) + (v3.x+v3.y+v3.z+v3.w);
    }
    __syncthreads();
    if (tid < 32) {      // suffix scan of 256 chunks
        float loc[8];
        float run = 0.f;
        #pragma unroll
        for (int i = 7; i >= 0; i--) { run += chunk[tid*8 + i]; loc[i] = run; }
        float t_l = run, suf = run;
        #pragma unroll
        for (int off = 1; off < 32; off <<= 1) {
            float v = __shfl_down_sync(0xffffffffu, suf, off);
            if (tid + off < 32) suf += v;
        }
        float above = suf - t_l;
        #pragma unroll
        for (int i = 0; i < 8; i++) csuf[tid*8 + i] = loc[i] + above;
        if (tid == 0) csuf[256] = 0.f;
    }
    __syncthreads();

    const float4* nb4 = reinterpret_cast<const float4*>(nbuf);
    for (int m = warp; m <= 256; m += 16) {
        const float4* base = nb4 + m*4;      // window starts at fine bin 16m-256
        float acc = 0.f;
        #pragma unroll
        for (int q = 0; q < 4; q++) {
            float4 x = base[q*32 + lane];
            acc += x.x*t[q].x + x.y*t[q].y + x.z*t[q].z + x.w*t[q].w;
        }
        #pragma unroll
        for (int off = 16; off; off >>= 1)
            acc += __shfl_down_sync(0xffffffffu, acc, off);
        if (lane == 0) {
            int cc = m + 16;
            float S = (cc < 256) ? csuf[cc] : 0.f;
            g_T[ct*257 + m] = S + acc;
        }
    }
}

// ---- k3: CDF L1 reduction to scalar ----
__global__ void __launch_bounds__(512) k3_loss(float* __restrict__ out) {
    __shared__ float red[16];
    const int tid = threadIdx.x;
    float s = 0.f;
    for (int e = tid; e < NCH*256; e += 512) {
        int p  = e >> 8;
        int bb = e & 255;
        const float* Tp = g_T + p*257;
        const float* Tt = g_T + (NCH + p)*257;
        float p0 = Tp[0], t0 = Tt[0];
        float invp = 1.f / (p0 - Tp[256]);
        float invt = 1.f / (t0 - Tt[256]);
        float cp  = (p0 - Tp[bb+1]) * invp;
        float ctv = (t0 - Tt[bb+1]) * invt;
        s += fabsf(cp - ctv);
    }
    #pragma unroll
    for (int off = 16; off; off >>= 1) s += __shfl_down_sync(0xffffffffu, s, off);
    if ((tid & 31) == 0) red[tid >> 5] = s;
    __syncthreads();
    if (tid < 32) {
        float v = (tid < 16) ? red[tid] : 0.f;
        #pragma unroll
        for (int off = 16; off; off >>= 1) v += __shfl_down_sync(0xffffffffu, v, off);
        if (tid == 0) out[0] = v * (1.0f / (48.0f * 256.0f));
    }
}

extern "C" void kernel_launch(void* const* d_in, const int* in_sizes, int n_in,
                              void* d_out, int out_size) {
    const float* pred = (const float*)d_in[0];
    const float* tgt  = (const float*)d_in[1];
    float* out = (float*)d_out;

    cudaFuncSetAttribute(k1_hist, cudaFuncAttributeMaxDynamicSharedMemorySize, K1_SMEM);

    k1_hist<<<dim3(NCT, NSLICE), 512, K1_SMEM>>>(pred, tgt);
    k2_T<<<NCT, 512>>>();
    k3_loss<<<1, 512>>>(out);
}

// round 5
// speedup vs baseline: 1.9570x; 1.1595x over previous
#include <cuda_runtime.h>
#include <math.h>

#define F_BINS   4096
#define W_HALF   256
#define TAPS     (2*W_HALF)            // 512
#define NBUF_LEN (F_BINS + 2*W_HALF)   // 4608
#define NCH      48
#define NCT      96
#define NSLICE   4
#define HW_IN    (512*512)
#define BROWS    16
#define HROWS    (2*BROWS + 2)         // 34
#define USTEP    0.0732421875f         // 300/4096

// scratch (static device globals -- zero-initialized at module load, no allocation)
__device__ __align__(16) unsigned int g_hist[NCT * NSLICE * F_BINS];  // 6.3 MB
__device__ __align__(16) float g_T[NCT * 257];
__device__ int g_done_ct[NCT];
__device__ int g_done_all;

#define K1_SMEM (F_BINS*4 + HROWS*256*4)   // 16384 + 34816 = 51200

__global__ void __launch_bounds__(512) k_all(const float* __restrict__ pred,
                                             const float* __restrict__ tgt,
                                             float* __restrict__ out) {
    extern __shared__ unsigned char smraw[];
    unsigned int* sh_hist = reinterpret_cast<unsigned int*>(smraw);
    float* sh_h = reinterpret_cast<float*>(smraw + F_BINS*4);   // [HROWS][256]
    __shared__ int s_ticket;
    __shared__ float s_red[16];

    const int ct    = blockIdx.x;   // 0..95
    const int slice = blockIdx.y;   // 0..3
    const int tid   = threadIdx.x;
    const int warp  = tid >> 5, lane = tid & 31;
    const unsigned FULL = 0xffffffffu;

    const int r0 = slice * 64;
    const int r1 = r0 + 64;

    const float* src = (ct < NCH) ? (pred + (size_t)ct * HW_IN)
                                  : (tgt  + (size_t)(ct - NCH) * HW_IN);

    // ================= Phase A: resize + slice histogram =================
    for (int i = tid; i < F_BINS; i += 512) sh_hist[i] = 0u;
    __syncthreads();

    for (int oyb = r0; oyb < r1; oyb += BROWS) {
        for (int lr = warp; lr < HROWS; lr += 16) {
            int iy = 2*oyb - 1 + lr;
            iy = iy < 0 ? 0 : (iy > 511 ? 511 : iy);
            const float4* row4 = reinterpret_cast<const float4*>(src + (size_t)iy * 512);
            float4 v0 = row4[lane];
            float4 v1 = row4[32 + lane];
            float4 v2 = row4[64 + lane];
            float4 v3 = row4[96 + lane];
            float cl1 = __shfl_sync(FULL, v0.w, 31);
            float cl2 = __shfl_sync(FULL, v1.w, 31);
            float cl3 = __shfl_sync(FULL, v2.w, 31);
            float cr0 = __shfl_sync(FULL, v1.x, 0);
            float cr1 = __shfl_sync(FULL, v2.x, 0);
            float cr2 = __shfl_sync(FULL, v3.x, 0);
            float carryL[4] = {0.f, cl1, cl2, cl3};
            float carryR[4] = {cr0, cr1, cr2, 0.f};
            float4 vv[4] = {v0, v1, v2, v3};
            float2* hd = reinterpret_cast<float2*>(sh_h + lr*256);
            #pragma unroll
            for (int c = 0; c < 4; c++) {
                float4 v = vv[c];
                float left  = __shfl_up_sync(FULL, v.w, 1);
                if (lane == 0)  left  = carryL[c];
                float right = __shfl_down_sync(FULL, v.x, 1);
                if (lane == 31) right = carryR[c];
                float ha, hb;
                if (c == 0 && lane == 0)
                    ha = (3.f*v.x + 3.f*v.y + v.z) * (1.f/7.f);
                else
                    ha = (left + 3.f*v.x + 3.f*v.y + v.z) * 0.125f;
                if (c == 3 && lane == 31)
                    hb = (v.y + 3.f*v.z + 3.f*v.w) * (1.f/7.f);
                else
                    hb = (v.y + 3.f*v.z + 3.f*v.w + right) * 0.125f;
                hd[c*32 + lane] = make_float2(ha, hb);
            }
        }
        __syncthreads();

        for (int p = tid; p < BROWS*256; p += 512) {
            int oyl = p >> 8;
            int ox  = p & 255;
            int oy  = oyb + oyl;
            const float* hp = sh_h + (2*oyl)*256 + ox;
            float a0 = hp[0], a1 = hp[256], a2 = hp[512], a3 = hp[768];
            float inv = (oy == 0 || oy == 255) ? (1.f/7.f) : 0.125f;
            float w0 = (oy == 0)   ? 0.f : inv;
            float w3 = (oy == 255) ? 0.f : inv;
            float val = w0*a0 + 3.f*inv*(a1 + a2) + w3*a3;
            int bin = (int)(val * (float)F_BINS);
            bin = bin < 0 ? 0 : (bin > F_BINS-1 ? F_BINS-1 : bin);
            atomicAdd(&sh_hist[bin], 1u);
        }
        __syncthreads();
    }

    {
        unsigned int* dst = g_hist + (size_t)(ct*NSLICE + slice) * F_BINS;
        const uint4* s4 = reinterpret_cast<const uint4*>(sh_hist);
        uint4* d4 = reinterpret_cast<uint4*>(dst);
        for (int i = tid; i < F_BINS/4; i += 512) d4[i] = s4[i];
    }

    // ================= Ticket: last slice of this ct proceeds =================
    __syncthreads();
    __threadfence();
    if (tid == 0) s_ticket = atomicAdd(&g_done_ct[ct], 1);
    __syncthreads();
    if (s_ticket != NSLICE - 1) return;
    if (tid == 0) atomicExch(&g_done_ct[ct], 0);   // self-reset for next replay

    // ================= Phase B: T(m) for this ct =================
    float* nbuf  = reinterpret_cast<float*>(smraw);       // [4608]
    float* tab   = nbuf + NBUF_LEN;                       // [512]
    float* csuf  = tab + TAPS;                            // [257]
    float* chunk = csuf + 257;                            // [256]

    __syncthreads();   // retire phase-A smem use before aliasing

    const unsigned int* h0 = g_hist + (size_t)(NSLICE*ct) * F_BINS;
    if (tid < W_HALF) {
        nbuf[tid] = 0.f;
        nbuf[W_HALF + F_BINS + tid] = 0.f;
    }
    for (int k = tid; k < F_BINS; k += 512)
        nbuf[W_HALF + k] = (float)(__ldcg(&h0[k]) + __ldcg(&h0[F_BINS + k])
                                 + __ldcg(&h0[2*F_BINS + k]) + __ldcg(&h0[3*F_BINS + k]));
    if (tid < TAPS)
        tab[tid] = 1.f / (1.f + expf(-USTEP * ((float)tid - 255.5f)));
    __syncthreads();

    if (tid < 256) {
        const float4* p4 = reinterpret_cast<const float4*>(nbuf + W_HALF) + tid*4;
        float4 v0 = p4[0], v1 = p4[1], v2 = p4[2], v3 = p4[3];
        chunk[tid] = (v0.x+v0.y+v0.z+v0.w) + (v1.x+v1.y+v1.z+v1.w)
                   + (v2.x+v2.y+v2.z+v2.w) + (v3.x+v3.y+v3.z+v3.w);
    }
    __syncthreads();
    if (tid < 32) {      // suffix scan of 256 chunks
        float loc[8];
        float run = 0.f;
        #pragma unroll
        for (int i = 7; i >= 0; i--) { run += chunk[tid*8 + i]; loc[i] = run; }
        float t_l = run, suf = run;
        #pragma unroll
        for (int off = 1; off < 32; off <<= 1) {
            float v = __shfl_down_sync(FULL, suf, off);
            if (tid + off < 32) suf += v;
        }
        float above = suf - t_l;
        #pragma unroll
        for (int i = 0; i < 8; i++) csuf[tid*8 + i] = loc[i] + above;
        if (tid == 0) csuf[256] = 0.f;
    }
    __syncthreads();

    const float4* nb4 = reinterpret_cast<const float4*>(nbuf);
    const float4* tb4 = reinterpret_cast<const float4*>(tab);
    for (int m = warp; m <= 256; m += 16) {
        const float4* base = nb4 + m*4;      // window starts at fine bin 16m-256
        float acc = 0.f;
        #pragma unroll
        for (int q = 0; q < 4; q++) {
            float4 x = base[q*32 + lane];
            float4 tq = tb4[q*32 + lane];
            acc += x.x*tq.x + x.y*tq.y + x.z*tq.z + x.w*tq.w;
        }
        #pragma unroll
        for (int off = 16; off; off >>= 1)
            acc += __shfl_down_sync(FULL, acc, off);
        if (lane == 0) {
            int cc = m + 16;
            float S = (cc < 256) ? csuf[cc] : 0.f;
            g_T[ct*257 + m] = S + acc;
        }
    }

    // ================= Ticket 2: last ct does final reduction =================
    __syncthreads();
    __threadfence();
    if (tid == 0) s_ticket = atomicAdd(&g_done_all, 1);
    __syncthreads();
    if (s_ticket != NCT - 1) return;
    if (tid == 0) atomicExch(&g_done_all, 0);   // self-reset

    // ================= Phase C: CDF L1 reduction =================
    float s = 0.f;
    for (int e = tid; e < NCH*256; e += 512) {
        int p  = e >> 8;
        int bb = e & 255;
        const float* Tp = g_T + p*257;
        const float* Tt = g_T + (NCH + p)*257;
        float p0 = __ldcg(&Tp[0]), t0 = __ldcg(&Tt[0]);
        float pe = __ldcg(&Tp[256]), te = __ldcg(&Tt[256]);
        float invp = 1.f / (p0 - pe);
        float invt = 1.f / (t0 - te);
        float cp  = (p0 - __ldcg(&Tp[bb+1])) * invp;
        float ctv = (t0 - __ldcg(&Tt[bb+1])) * invt;
        s += fabsf(cp - ctv);
    }
    #pragma unroll
    for (int off = 16; off; off >>= 1) s += __shfl_down_sync(FULL, s, off);
    if (lane == 0) s_red[warp] = s;
    __syncthreads();
    if (tid < 32) {
        float v = (tid < 16) ? s_red[tid] : 0.f;
        #pragma unroll
        for (int off = 16; off; off >>= 1) v += __shfl_down_sync(FULL, v, off);
        if (tid == 0) out[0] = v * (1.0f / (48.0f * 256.0f));
    }
}

extern "C" void kernel_launch(void* const* d_in, const int* in_sizes, int n_in,
                              void* d_out, int out_size) {
    const float* pred = (const float*)d_in[0];
    const float* tgt  = (const float*)d_in[1];
    float* out = (float*)d_out;

    cudaFuncSetAttribute(k_all, cudaFuncAttributeMaxDynamicSharedMemorySize, K1_SMEM);
    k_all<<<dim3(NCT, NSLICE), 512, K1_SMEM>>>(pred, tgt, out);
}